// round 1
// baseline (speedup 1.0000x reference)
#include <cuda_runtime.h>

// Sizes
#define NN 512
#define RR 16
#define HH 16
#define TI 4              // i-rows per block
#define NB (NN/TI)        // 128 blocks
#define JC 16             // j chunk

// Scratch (module globals: allowed; no runtime allocation)
__device__ float g_sm[NB*NN*RR*TI];      // [ib][(j*RR + r)*TI + ti]  (16MB)
__device__ float g_diffn[NB*NN*TI*3];    // [ib][j][ti][b]            (3MB)
__device__ float g_bk[NN*HH*3];          // [i][c][b]
__device__ float g_bq[NN*HH*3];
__device__ float g_S[NN*RR*3];           // [i][r][b]
__device__ float g_lr[NN*1024];          // MLP1 output: left(512)|right(512)

// ---------------------------------------------------------------------------
// Phase A: per-pair smearing + first contraction (bk, bq) + basis j-sum (S)
// ---------------------------------------------------------------------------
__global__ __launch_bounds__(256) void phaseA(const float* __restrict__ x,
                                              const float* __restrict__ W)
{
    const float* Kw = W;                 // W[0] : (N,R,H)
    const float* Qw = W + NN*RR*HH;      // W[1]
    const int ib = blockIdx.x;
    const int i0 = ib * TI;
    const int tid = threadIdx.x;
    const int jj = tid >> 4;             // 0..15
    const int cr = tid & 15;             // 0..15 (doubles as r in step2, c in step3)

    __shared__ float s_xi[TI][3];
    __shared__ float s_diffn[JC][TI][3];
    __shared__ float s_e[TI][JC];
    __shared__ float s_cut[TI][JC];
    __shared__ __align__(16) float s_sm[JC][RR][TI];
    __shared__ float s_red[JC][HH*TI*3]; // 16 x 192 reduction buffer

    if (tid < TI*3) s_xi[tid/3][tid%3] = x[i0*3 + tid];

    // smearing constants (f32, matches jnp float32 path)
    const float start = 0.006737946999085467f;          // exp(-5)
    const float mstep = (1.0f - start) * (1.0f/15.0f);
    const float sbeta = 0.125f * (1.0f - start);
    const float beta  = 1.0f / (sbeta * sbeta);
    const float meanr = start + mstep * (float)cr;

    float acc_bk[TI][3], acc_bq[TI][3], accS[TI][3];
    #pragma unroll
    for (int t = 0; t < TI; t++)
        #pragma unroll
        for (int b = 0; b < 3; b++) { acc_bk[t][b]=0.f; acc_bq[t][b]=0.f; accS[t][b]=0.f; }

    __syncthreads();

    for (int j0 = 0; j0 < NN; j0 += JC) {
        // ---- step1: per-pair geometry (64 lead threads) ----
        if (tid < TI*JC) {
            int ti = tid >> 4, jl = tid & 15;
            int j = j0 + jl;
            float dx = s_xi[ti][0] - x[j*3+0];
            float dy = s_xi[ti][1] - x[j*3+1];
            float dz = s_xi[ti][2] - x[j*3+2];
            float nsq = dx*dx + dy*dy + dz*dz + 1e-6f;
            float d   = sqrtf(nsq);
            float inv = 1.0f / nsq;
            float d0 = dx*inv, d1 = dy*inv, d2 = dz*inv;
            s_diffn[jl][ti][0] = d0; s_diffn[jl][ti][1] = d1; s_diffn[jl][ti][2] = d2;
            int gi = ib*(NN*TI*3) + j*(TI*3) + ti*3;
            g_diffn[gi+0] = d0; g_diffn[gi+1] = d1; g_diffn[gi+2] = d2;
            s_e[ti][jl]   = __expf(-d);
            s_cut[ti][jl] = (d < 5.0f) ? 0.5f*(__cosf(d*0.6283185307179586f) + 1.0f) : 0.0f;
        }
        __syncthreads();

        // ---- step2: sm[i,j,r] for r=cr, plus S partials ----
        {
            float sm4[TI];
            #pragma unroll
            for (int ti = 0; ti < TI; ti++) {
                float e  = s_e[ti][jj];
                float u  = e - meanr;
                float sm = s_cut[ti][jj] * __expf(-beta*u*u);
                sm4[ti] = sm;
                s_sm[jj][cr][ti] = sm;
                accS[ti][0] += sm * s_diffn[jj][ti][0];
                accS[ti][1] += sm * s_diffn[jj][ti][1];
                accS[ti][2] += sm * s_diffn[jj][ti][2];
            }
            float4 v = make_float4(sm4[0], sm4[1], sm4[2], sm4[3]);
            *(float4*)&g_sm[ib*(NN*RR*TI) + ((j0+jj)*RR + cr)*TI] = v;
        }
        __syncthreads();

        // ---- step3: P = sm @ K/Q  then bk/bq accumulation ----
        {
            int j = j0 + jj;
            float pK[TI] = {0,0,0,0}, pQ[TI] = {0,0,0,0};
            const float* kp = Kw + j*(RR*HH) + cr;
            const float* qp = Qw + j*(RR*HH) + cr;
            #pragma unroll
            for (int r = 0; r < RR; r++) {
                float4 s4 = *(const float4*)&s_sm[jj][r][0];
                float kv = kp[r*HH];
                float qv = qp[r*HH];
                pK[0] += s4.x*kv; pK[1] += s4.y*kv; pK[2] += s4.z*kv; pK[3] += s4.w*kv;
                pQ[0] += s4.x*qv; pQ[1] += s4.y*qv; pQ[2] += s4.z*qv; pQ[3] += s4.w*qv;
            }
            #pragma unroll
            for (int ti = 0; ti < TI; ti++) {
                float d0 = s_diffn[jj][ti][0], d1 = s_diffn[jj][ti][1], d2 = s_diffn[jj][ti][2];
                acc_bk[ti][0] += pK[ti]*d0; acc_bk[ti][1] += pK[ti]*d1; acc_bk[ti][2] += pK[ti]*d2;
                acc_bq[ti][0] += pQ[ti]*d0; acc_bq[ti][1] += pQ[ti]*d1; acc_bq[ti][2] += pQ[ti]*d2;
            }
        }
        __syncthreads();
    }

    // ---- epilogue: reduce over jj partials ----
    #pragma unroll
    for (int t = 0; t < TI; t++)
        #pragma unroll
        for (int b = 0; b < 3; b++) s_red[jj][cr*12 + t*3 + b] = acc_bk[t][b];
    __syncthreads();
    if (tid < 192) {
        int c = tid/12, rest = tid%12, ti = rest/3, b = rest%3;
        float s = 0.f;
        #pragma unroll
        for (int q = 0; q < 16; q++) s += s_red[q][c*12 + ti*3 + b];
        g_bk[(i0+ti)*48 + c*3 + b] = s;
    }
    __syncthreads();
    #pragma unroll
    for (int t = 0; t < TI; t++)
        #pragma unroll
        for (int b = 0; b < 3; b++) s_red[jj][cr*12 + t*3 + b] = acc_bq[t][b];
    __syncthreads();
    if (tid < 192) {
        int c = tid/12, rest = tid%12, ti = rest/3, b = rest%3;
        float s = 0.f;
        #pragma unroll
        for (int q = 0; q < 16; q++) s += s_red[q][c*12 + ti*3 + b];
        g_bq[(i0+ti)*48 + c*3 + b] = s;
    }
    __syncthreads();
    #pragma unroll
    for (int t = 0; t < TI; t++)
        #pragma unroll
        for (int b = 0; b < 3; b++) s_red[jj][cr*12 + t*3 + b] = accS[t][b];
    __syncthreads();
    if (tid < 192) {
        int r = tid/12, rest = tid%12, ti = rest/3, b = rest%3;
        float s = 0.f;
        #pragma unroll
        for (int q = 0; q < 16; q++) s += s_red[q][r*12 + ti*3 + b];
        g_S[(i0+ti)*48 + r*3 + b] = s;
    }
}

// ---------------------------------------------------------------------------
// Phase B: att = bk·bq outer; MLP1: left|right = silu(att@W1^T + b1)@W2^T
// ---------------------------------------------------------------------------
__global__ __launch_bounds__(256) void phaseB(const float* __restrict__ W1,
                                              const float* __restrict__ b1,
                                              const float* __restrict__ W2)
{
    const int i = blockIdx.x;
    const int tid = threadIdx.x;
    __shared__ float s_bk[48], s_bq[48], s_att[256], s_y[16];

    if (tid < 48)       s_bk[tid]     = g_bk[i*48 + tid];
    else if (tid < 96)  s_bq[tid-48]  = g_bq[i*48 + tid - 48];
    __syncthreads();

    int h = tid >> 4, g = tid & 15;
    s_att[tid] = s_bk[h*3+0]*s_bq[g*3+0] + s_bk[h*3+1]*s_bq[g*3+1] + s_bk[h*3+2]*s_bq[g*3+2];
    __syncthreads();

    if (tid < 16) {
        float y = b1[tid];
        const float* w = W1 + tid*256;
        #pragma unroll 8
        for (int k = 0; k < 256; k++) y += s_att[k]*w[k];
        s_y[tid] = y / (1.0f + __expf(-y));   // silu
    }
    __syncthreads();

    #pragma unroll
    for (int q = 0; q < 4; q++) {
        int m = tid + 256*q;
        const float* w = W2 + m*16;
        float a = 0.f;
        #pragma unroll
        for (int o = 0; o < 16; o++) a += s_y[o]*w[o];
        g_lr[i*1024 + m] = a;
    }
}

// ---------------------------------------------------------------------------
// Phase C: second contraction (decomposed: right-stream + left⊗S) + MLP2 + out
// ---------------------------------------------------------------------------
__global__ __launch_bounds__(256) void phaseC(const float* __restrict__ W3,
                                              const float* __restrict__ b3,
                                              const float* __restrict__ W4,
                                              const float* __restrict__ b4,
                                              float* __restrict__ out)
{
    const int ib = blockIdx.x;
    const int i0 = ib * TI;
    const int tid = threadIdx.x;
    const int jj = tid >> 4;
    const int cr = tid & 15;

    __shared__ float s_diffn[JC][TI][3];
    __shared__ float s_red[JC][HH*TI*3];
    __shared__ float s_bk2[TI][HH][3], s_bq2[TI][HH][3];
    __shared__ float s_att[256];
    __shared__ float s_y[16];

    float acc_bk[TI][3], acc_bq[TI][3];
    #pragma unroll
    for (int t = 0; t < TI; t++)
        #pragma unroll
        for (int b = 0; b < 3; b++) { acc_bk[t][b]=0.f; acc_bq[t][b]=0.f; }

    for (int j0 = 0; j0 < NN; j0 += JC) {
        if (tid < TI*JC*3)
            ((float*)s_diffn)[tid] = g_diffn[ib*(NN*TI*3) + j0*(TI*3) + tid];
        __syncthreads();

        {
            int j = j0 + jj;
            const float* smp = &g_sm[ib*(NN*RR*TI) + (j*RR)*TI];
            const float* rkp = g_lr + j*1024 + 512 + cr;   // right-K base
            float pK[TI] = {0,0,0,0}, pQ[TI] = {0,0,0,0};
            #pragma unroll
            for (int r = 0; r < RR; r++) {
                float4 s4 = *(const float4*)&smp[r*TI];
                float kv = rkp[r*16];          // right[:, r*16+c]
                float qv = rkp[256 + r*16];    // right[:, 256+r*16+c]
                pK[0] += s4.x*kv; pK[1] += s4.y*kv; pK[2] += s4.z*kv; pK[3] += s4.w*kv;
                pQ[0] += s4.x*qv; pQ[1] += s4.y*qv; pQ[2] += s4.z*qv; pQ[3] += s4.w*qv;
            }
            #pragma unroll
            for (int ti = 0; ti < TI; ti++) {
                float d0 = s_diffn[jj][ti][0], d1 = s_diffn[jj][ti][1], d2 = s_diffn[jj][ti][2];
                acc_bk[ti][0] += pK[ti]*d0; acc_bk[ti][1] += pK[ti]*d1; acc_bk[ti][2] += pK[ti]*d2;
                acc_bq[ti][0] += pQ[ti]*d0; acc_bq[ti][1] += pQ[ti]*d1; acc_bq[ti][2] += pQ[ti]*d2;
            }
        }
        __syncthreads();
    }

    // reduce bk2 over jj, add left-term  sum_r left[i,r*16+c] * S[i,r,b]
    #pragma unroll
    for (int t = 0; t < TI; t++)
        #pragma unroll
        for (int b = 0; b < 3; b++) s_red[jj][cr*12 + t*3 + b] = acc_bk[t][b];
    __syncthreads();
    if (tid < 192) {
        int c = tid/12, rest = tid%12, ti = rest/3, b = rest%3;
        float s = 0.f;
        #pragma unroll
        for (int q = 0; q < 16; q++) s += s_red[q][c*12 + ti*3 + b];
        const float* lp = g_lr + (i0+ti)*1024 + c;   // left-K
        const float* sp = g_S  + (i0+ti)*48 + b;
        #pragma unroll
        for (int r = 0; r < 16; r++) s += lp[r*16] * sp[r*3];
        s_bk2[ti][c][b] = s;
    }
    __syncthreads();
    #pragma unroll
    for (int t = 0; t < TI; t++)
        #pragma unroll
        for (int b = 0; b < 3; b++) s_red[jj][cr*12 + t*3 + b] = acc_bq[t][b];
    __syncthreads();
    if (tid < 192) {
        int c = tid/12, rest = tid%12, ti = rest/3, b = rest%3;
        float s = 0.f;
        #pragma unroll
        for (int q = 0; q < 16; q++) s += s_red[q][c*12 + ti*3 + b];
        const float* lp = g_lr + (i0+ti)*1024 + 256 + c;  // left-Q
        const float* sp = g_S  + (i0+ti)*48 + b;
        #pragma unroll
        for (int r = 0; r < 16; r++) s += lp[r*16] * sp[r*3];
        s_bq2[ti][c][b] = s;
    }
    __syncthreads();

    // final MLP + output, one i at a time
    for (int ti = 0; ti < TI; ti++) {
        int h = tid >> 4, g = tid & 15;
        s_att[tid] = s_bk2[ti][h][0]*s_bq2[ti][g][0]
                   + s_bk2[ti][h][1]*s_bq2[ti][g][1]
                   + s_bk2[ti][h][2]*s_bq2[ti][g][2];
        __syncthreads();
        if (tid < 16) {
            float y = b3[tid];
            const float* w = W3 + tid*256;
            #pragma unroll 8
            for (int k = 0; k < 256; k++) y += s_att[k]*w[k];
            s_y[tid] = y / (1.0f + __expf(-y));
        }
        __syncthreads();
        if (tid == 0) {
            float a = b4[0];
            #pragma unroll
            for (int o = 0; o < 16; o++) a += s_y[o]*W4[o];
            out[i0 + ti] = a;
        }
        __syncthreads();
    }
}

// ---------------------------------------------------------------------------
extern "C" void kernel_launch(void* const* d_in, const int* in_sizes, int n_in,
                              void* d_out, int out_size)
{
    const float* x  = (const float*)d_in[0];
    const float* W  = (const float*)d_in[1];
    const float* W1 = (const float*)d_in[2];
    const float* b1 = (const float*)d_in[3];
    const float* W2 = (const float*)d_in[4];
    const float* W3 = (const float*)d_in[5];
    const float* b3 = (const float*)d_in[6];
    const float* W4 = (const float*)d_in[7];
    const float* b4 = (const float*)d_in[8];
    float* out = (float*)d_out;

    phaseA<<<NB, 256>>>(x, W);
    phaseB<<<NN, 256>>>(W1, b1, W2);
    phaseC<<<NB, 256>>>(W3, b3, W4, b4, out);
}

// round 2
// speedup vs baseline: 2.8291x; 2.8291x over previous
#include <cuda_runtime.h>

#define NN 512
#define RR 16
#define HH 16
#define TI 4               // i-rows per warp task
#define JS 32              // j slices
#define JPW (NN/JS)        // 16 j per warp task
#define NIG (NN/TI)        // 128 i-groups
#define BLK 256
#define GRID_AC ((NIG*JS)/(BLK/32))   // 512 blocks

// smearing constants (f32)
#define SM_START 0.006737946999085467f
#define SM_MSTEP ((1.0f - SM_START) * (1.0f/15.0f))
#define SM_SBETA (0.125f * (1.0f - SM_START))
#define SM_BETA  (1.0f / (SM_SBETA * SM_SBETA))
#define PI_OVER5 0.6283185307179586f

// scratch
__device__ float g_sm[NN*NN*RR];       // [i][j][r]      16MB
__device__ float g_diffn[NN*NN*3];     // [i][j][b]       3MB
__device__ float g_bkp [JS*NN*48];     // per-slice partials [js][i][c*3+b]
__device__ float g_bqp [JS*NN*48];
__device__ float g_Sp  [JS*NN*48];     // [js][i][r*3+b]
__device__ float g_S   [NN*48];        // merged S
__device__ float g_lr  [NN*1024];      // MLP1 out: left(512)|right(512)
__device__ float g_bk2p[JS*NN*48];
__device__ float g_bq2p[JS*NN*48];

// ---------------------------------------------------------------------------
// Phase A: warp-autonomous. Warp = (i-group of 4, j-slice of 16).
// Lanes 0-15: K path (c = lane), lanes 16-31: Q path (c = lane-16).
// sm[r] computed with r = lane&15, broadcast via shfl.
// ---------------------------------------------------------------------------
__global__ __launch_bounds__(BLK) void phaseA(const float* __restrict__ x,
                                              const float* __restrict__ W)
{
    const float* Kw = W;
    const float* Qw = W + NN*RR*HH;

    const int wid  = blockIdx.x * (BLK/32) + (threadIdx.x >> 5);
    const int lane = threadIdx.x & 31;
    const int ig   = wid >> 5;          // / JS
    const int js   = wid & (JS-1);
    const int i0   = ig * TI;
    const int c    = lane & 15;
    const bool isQ = lane >= 16;
    const float mean = SM_START + SM_MSTEP * (float)c;

    float xi[TI][3];
    #pragma unroll
    for (int t = 0; t < TI; t++)
        #pragma unroll
        for (int b = 0; b < 3; b++) xi[t][b] = __ldg(&x[(i0+t)*3 + b]);

    float accP[TI][3], accS[TI][3];
    #pragma unroll
    for (int t = 0; t < TI; t++)
        #pragma unroll
        for (int b = 0; b < 3; b++) { accP[t][b] = 0.f; accS[t][b] = 0.f; }

    const float* Wbase = isQ ? Qw : Kw;

    for (int jl = 0; jl < JPW; jl++) {
        const int j = js * JPW + jl;
        const float xj0 = __ldg(&x[j*3+0]);
        const float xj1 = __ldg(&x[j*3+1]);
        const float xj2 = __ldg(&x[j*3+2]);

        float d0[TI], d1[TI], d2[TI], smv[TI];
        #pragma unroll
        for (int t = 0; t < TI; t++) {
            float dx = xi[t][0] - xj0;
            float dy = xi[t][1] - xj1;
            float dz = xi[t][2] - xj2;
            float nsq = fmaf(dx,dx, fmaf(dy,dy, fmaf(dz,dz, 1e-6f)));
            float rin = rsqrtf(nsq);
            float d   = nsq * rin;          // sqrt(nsq)
            float inv = rin * rin;          // 1/nsq
            d0[t] = dx * inv; d1[t] = dy * inv; d2[t] = dz * inv;
            float e = __expf(-d);
            float cut = 0.f;
            if (d < 5.0f) cut = 0.5f * (__cosf(d * PI_OVER5) + 1.0f);
            float u = e - mean;
            smv[t] = cut * __expf(-SM_BETA * u * u);
            accS[t][0] = fmaf(smv[t], d0[t], accS[t][0]);
            accS[t][1] = fmaf(smv[t], d1[t], accS[t][1]);
            accS[t][2] = fmaf(smv[t], d2[t], accS[t][2]);
            if (!isQ) g_sm[((i0+t)*NN + j)*16 + c] = smv[t];
            if (lane >= 16 && lane < 19) {
                float v = (lane == 16) ? d0[t] : (lane == 17) ? d1[t] : d2[t];
                g_diffn[((i0+t)*NN + j)*3 + (lane-16)] = v;
            }
        }

        // P[ti][c] = sum_r smv[ti][r] * W[j,r,c]
        const float* wp = Wbase + j*(RR*HH) + c;
        float P[TI] = {0.f, 0.f, 0.f, 0.f};
        #pragma unroll
        for (int r = 0; r < RR; r++) {
            float w = __ldg(wp + r*HH);
            P[0] = fmaf(__shfl_sync(0xffffffffu, smv[0], r), w, P[0]);
            P[1] = fmaf(__shfl_sync(0xffffffffu, smv[1], r), w, P[1]);
            P[2] = fmaf(__shfl_sync(0xffffffffu, smv[2], r), w, P[2]);
            P[3] = fmaf(__shfl_sync(0xffffffffu, smv[3], r), w, P[3]);
        }
        #pragma unroll
        for (int t = 0; t < TI; t++) {
            accP[t][0] = fmaf(P[t], d0[t], accP[t][0]);
            accP[t][1] = fmaf(P[t], d1[t], accP[t][1]);
            accP[t][2] = fmaf(P[t], d2[t], accP[t][2]);
        }
    }

    float* outp = isQ ? g_bqp : g_bkp;
    #pragma unroll
    for (int t = 0; t < TI; t++)
        #pragma unroll
        for (int b = 0; b < 3; b++)
            outp[(js*NN + (i0+t))*48 + c*3 + b] = accP[t][b];
    if (!isQ) {
        #pragma unroll
        for (int t = 0; t < TI; t++)
            #pragma unroll
            for (int b = 0; b < 3; b++)
                g_Sp[(js*NN + (i0+t))*48 + c*3 + b] = accS[t][b];   // c == r here
    }
}

// ---------------------------------------------------------------------------
// Phase B: merge partials, att = bk·bq outer, MLP1 -> g_lr; also merge S.
// ---------------------------------------------------------------------------
__global__ __launch_bounds__(256) void phaseB(const float* __restrict__ W1,
                                              const float* __restrict__ b1,
                                              const float* __restrict__ W2)
{
    const int i = blockIdx.x;
    const int tid = threadIdx.x;
    __shared__ float s_bk[48], s_bq[48], s_att[256], s_y[16];

    if (tid < 48) {
        float s = 0.f;
        #pragma unroll
        for (int js = 0; js < JS; js++) s += g_bkp[(js*NN + i)*48 + tid];
        s_bk[tid] = s;
    } else if (tid < 96) {
        float s = 0.f;
        #pragma unroll
        for (int js = 0; js < JS; js++) s += g_bqp[(js*NN + i)*48 + (tid-48)];
        s_bq[tid-48] = s;
    } else if (tid < 144) {
        float s = 0.f;
        #pragma unroll
        for (int js = 0; js < JS; js++) s += g_Sp[(js*NN + i)*48 + (tid-96)];
        g_S[i*48 + (tid-96)] = s;
    }
    __syncthreads();

    {
        int h = tid >> 4, g = tid & 15;
        s_att[tid] = s_bk[h*3+0]*s_bq[g*3+0] + s_bk[h*3+1]*s_bq[g*3+1]
                   + s_bk[h*3+2]*s_bq[g*3+2];
    }
    __syncthreads();

    // y[h] = silu(b1[h] + att . W1[h,:]) — 16 threads per h, shfl reduce
    {
        int h = tid >> 4, t = tid & 15;
        const float* w = W1 + h*256 + t;
        float p = 0.f;
        #pragma unroll
        for (int q = 0; q < 16; q++) p = fmaf(s_att[t + 16*q], w[16*q], p);
        #pragma unroll
        for (int m = 8; m >= 1; m >>= 1) p += __shfl_xor_sync(0xffffffffu, p, m, 16);
        if (t == 0) {
            float y = p + b1[h];
            s_y[h] = y / (1.0f + __expf(-y));
        }
    }
    __syncthreads();

    #pragma unroll
    for (int q = 0; q < 4; q++) {
        int m = tid + 256*q;
        const float* w = W2 + m*16;
        float a = 0.f;
        #pragma unroll
        for (int o = 0; o < 16; o++) a = fmaf(s_y[o], w[o], a);
        g_lr[i*1024 + m] = a;
    }
}

// ---------------------------------------------------------------------------
// Phase C: warp-autonomous second contraction (right-stream part).
// bk2p[i,c,b] += sum_{j in slice} diffn[i,j,b] * sum_r sm[i,j,r]*right[j,r*16+c]
// ---------------------------------------------------------------------------
__global__ __launch_bounds__(BLK) void phaseC()
{
    const int wid  = blockIdx.x * (BLK/32) + (threadIdx.x >> 5);
    const int lane = threadIdx.x & 31;
    const int ig   = wid >> 5;
    const int js   = wid & (JS-1);
    const int i0   = ig * TI;
    const int c    = lane & 15;
    const bool isQ = lane >= 16;

    float accP[TI][3];
    #pragma unroll
    for (int t = 0; t < TI; t++)
        #pragma unroll
        for (int b = 0; b < 3; b++) accP[t][b] = 0.f;

    const int lroff = 512 + (isQ ? 256 : 0) + c;

    for (int jl = 0; jl < JPW; jl++) {
        const int j = js * JPW + jl;

        float smv[TI], d0[TI], d1[TI], d2[TI];
        #pragma unroll
        for (int t = 0; t < TI; t++) {
            smv[t] = __ldg(&g_sm[((i0+t)*NN + j)*16 + c]);
            const float* dp = &g_diffn[((i0+t)*NN + j)*3];
            d0[t] = __ldg(dp+0); d1[t] = __ldg(dp+1); d2[t] = __ldg(dp+2);
        }

        const float* wp = g_lr + j*1024 + lroff;
        float P[TI] = {0.f, 0.f, 0.f, 0.f};
        #pragma unroll
        for (int r = 0; r < RR; r++) {
            float w = __ldg(wp + r*16);
            P[0] = fmaf(__shfl_sync(0xffffffffu, smv[0], r), w, P[0]);
            P[1] = fmaf(__shfl_sync(0xffffffffu, smv[1], r), w, P[1]);
            P[2] = fmaf(__shfl_sync(0xffffffffu, smv[2], r), w, P[2]);
            P[3] = fmaf(__shfl_sync(0xffffffffu, smv[3], r), w, P[3]);
        }
        #pragma unroll
        for (int t = 0; t < TI; t++) {
            accP[t][0] = fmaf(P[t], d0[t], accP[t][0]);
            accP[t][1] = fmaf(P[t], d1[t], accP[t][1]);
            accP[t][2] = fmaf(P[t], d2[t], accP[t][2]);
        }
    }

    float* outp = isQ ? g_bq2p : g_bk2p;
    #pragma unroll
    for (int t = 0; t < TI; t++)
        #pragma unroll
        for (int b = 0; b < 3; b++)
            outp[(js*NN + (i0+t))*48 + c*3 + b] = accP[t][b];
}

// ---------------------------------------------------------------------------
// Phase D: merge partials + left⊗S term, att outer, MLP2, output.
// ---------------------------------------------------------------------------
__global__ __launch_bounds__(256) void phaseD(const float* __restrict__ W3,
                                              const float* __restrict__ b3,
                                              const float* __restrict__ W4,
                                              const float* __restrict__ b4,
                                              float* __restrict__ out)
{
    const int i = blockIdx.x;
    const int tid = threadIdx.x;
    __shared__ float s_bk[48], s_bq[48], s_att[256], s_y[16];

    if (tid < 48) {
        int cc = tid/3, b = tid%3;
        float s = 0.f;
        #pragma unroll
        for (int js = 0; js < JS; js++) s += g_bk2p[(js*NN + i)*48 + tid];
        const float* lp = g_lr + i*1024 + cc;        // left-K
        const float* sp = g_S  + i*48 + b;
        #pragma unroll
        for (int r = 0; r < 16; r++) s = fmaf(lp[r*16], sp[r*3], s);
        s_bk[tid] = s;
    } else if (tid < 96) {
        int idx = tid - 48, cc = idx/3, b = idx%3;
        float s = 0.f;
        #pragma unroll
        for (int js = 0; js < JS; js++) s += g_bq2p[(js*NN + i)*48 + idx];
        const float* lp = g_lr + i*1024 + 256 + cc;  // left-Q
        const float* sp = g_S  + i*48 + b;
        #pragma unroll
        for (int r = 0; r < 16; r++) s = fmaf(lp[r*16], sp[r*3], s);
        s_bq[idx] = s;
    }
    __syncthreads();

    {
        int h = tid >> 4, g = tid & 15;
        s_att[tid] = s_bk[h*3+0]*s_bq[g*3+0] + s_bk[h*3+1]*s_bq[g*3+1]
                   + s_bk[h*3+2]*s_bq[g*3+2];
    }
    __syncthreads();

    {
        int h = tid >> 4, t = tid & 15;
        const float* w = W3 + h*256 + t;
        float p = 0.f;
        #pragma unroll
        for (int q = 0; q < 16; q++) p = fmaf(s_att[t + 16*q], w[16*q], p);
        #pragma unroll
        for (int m = 8; m >= 1; m >>= 1) p += __shfl_xor_sync(0xffffffffu, p, m, 16);
        if (t == 0) {
            float y = p + b3[h];
            s_y[h] = y / (1.0f + __expf(-y));
        }
    }
    __syncthreads();

    if (tid == 0) {
        float a = b4[0];
        #pragma unroll
        for (int o = 0; o < 16; o++) a = fmaf(s_y[o], W4[o], a);
        out[i] = a;
    }
}

// ---------------------------------------------------------------------------
extern "C" void kernel_launch(void* const* d_in, const int* in_sizes, int n_in,
                              void* d_out, int out_size)
{
    const float* x  = (const float*)d_in[0];
    const float* W  = (const float*)d_in[1];
    const float* W1 = (const float*)d_in[2];
    const float* b1 = (const float*)d_in[3];
    const float* W2 = (const float*)d_in[4];
    const float* W3 = (const float*)d_in[5];
    const float* b3 = (const float*)d_in[6];
    const float* W4 = (const float*)d_in[7];
    const float* b4 = (const float*)d_in[8];
    float* out = (float*)d_out;

    phaseA<<<GRID_AC, BLK>>>(x, W);
    phaseB<<<NN, 256>>>(W1, b1, W2);
    phaseC<<<GRID_AC, BLK>>>();
    phaseD<<<NN, 256>>>(W3, b3, W4, b4, out);
}

// round 3
// speedup vs baseline: 4.1681x; 1.4733x over previous
#include <cuda_runtime.h>

#define NN 512
#define RR 16
#define HH 16
#define TI 4               // i-rows per warp task
#define JS 32              // j slices
#define JPW (NN/JS)        // 16 j per warp task
#define NIG (NN/TI)        // 128 i-groups
#define BLK 256
#define GRID_AC ((NIG*JS)/(BLK/32))   // 512 blocks

// smearing constants (f32)
#define SM_START 0.006737946999085467f
#define SM_MSTEP ((1.0f - SM_START) * (1.0f/15.0f))
#define SM_SBETA (0.125f * (1.0f - SM_START))
#define SM_BETA  (1.0f / (SM_SBETA * SM_SBETA))
#define PI_OVER5 0.6283185307179586f

// scratch
__device__ __align__(16) float g_sm[NN*NN*RR];   // [i][j][r]  16MB (rows 64B aligned)
__device__ float4 g_diffn4[NN*NN];               // [i][j] -> (d0,d1,d2,0)  4MB
__device__ float g_bkp [JS*NN*48];               // per-slice partials [js][i][c*3+b]
__device__ float g_bqp [JS*NN*48];
__device__ float g_Sp  [JS*NN*48];               // [js][i][r*3+b]
__device__ float g_S   [NN*48];                  // merged S
__device__ float g_lr  [NN*1024];                // MLP1 out: left(512)|right(512)
__device__ float g_bk2p[JS*NN*48];
__device__ float g_bq2p[JS*NN*48];

// ---------------------------------------------------------------------------
// Phase A: warp = (i-group of 4, j-slice of 16). Lanes 0-15 K path, 16-31 Q.
// sm transposed through smem (STS + LDS.128), no shfl.
// ---------------------------------------------------------------------------
__global__ __launch_bounds__(BLK, 2) void phaseA(const float* __restrict__ x,
                                                 const float* __restrict__ W)
{
    __shared__ float s_x[NN*3];
    __shared__ __align__(16) float s_sm[BLK/32][TI][RR];

    const int tid = threadIdx.x;
    for (int k = tid; k < NN*3; k += BLK) s_x[k] = x[k];
    __syncthreads();

    const int w    = tid >> 5;
    const int lane = tid & 31;
    const int wid  = blockIdx.x * (BLK/32) + w;
    const int ig   = wid >> 5;          // / JS
    const int js   = wid & (JS-1);
    const int i0   = ig * TI;
    const int c    = lane & 15;
    const bool isQ = lane >= 16;
    const float mean = SM_START + SM_MSTEP * (float)c;

    const float* Wbase = W + (isQ ? NN*RR*HH : 0);

    float xi0[TI], xi1[TI], xi2[TI];
    #pragma unroll
    for (int t = 0; t < TI; t++) {
        xi0[t] = s_x[(i0+t)*3+0];
        xi1[t] = s_x[(i0+t)*3+1];
        xi2[t] = s_x[(i0+t)*3+2];
    }

    float accP[TI][3], accS[TI][3];
    #pragma unroll
    for (int t = 0; t < TI; t++)
        #pragma unroll
        for (int b = 0; b < 3; b++) { accP[t][b] = 0.f; accS[t][b] = 0.f; }

    #pragma unroll 2
    for (int jl = 0; jl < JPW; jl++) {
        const int j = js * JPW + jl;
        const float xj0 = s_x[j*3+0];
        const float xj1 = s_x[j*3+1];
        const float xj2 = s_x[j*3+2];

        float D0[TI], D1[TI], D2[TI];
        #pragma unroll
        for (int t = 0; t < TI; t++) {
            float dx = xi0[t]-xj0, dy = xi1[t]-xj1, dz = xi2[t]-xj2;
            float nsq = fmaf(dx,dx, fmaf(dy,dy, fmaf(dz,dz, 1e-6f)));
            float rin = rsqrtf(nsq);
            float d   = nsq * rin;
            float inv = rin * rin;
            D0[t] = dx*inv; D1[t] = dy*inv; D2[t] = dz*inv;
            float e   = __expf(-d);
            float cut = (d < 5.0f) ? 0.5f*(__cosf(d*PI_OVER5) + 1.0f) : 0.0f;
            float u   = e - mean;
            float sv  = cut * __expf(-SM_BETA*u*u);
            accS[t][0] = fmaf(sv, D0[t], accS[t][0]);
            accS[t][1] = fmaf(sv, D1[t], accS[t][1]);
            accS[t][2] = fmaf(sv, D2[t], accS[t][2]);
            if (!isQ) {
                s_sm[w][t][c] = sv;
                g_sm[((i0+t)*NN + j)*16 + c] = sv;
            }
            if (lane == 16+t)
                g_diffn4[(i0+t)*NN + j] = make_float4(D0[t], D1[t], D2[t], 0.f);
        }
        __syncwarp();

        // P[t] = sum_r s_sm[w][t][r] * W[j, r, c]
        const float* wp = Wbase + j*(RR*HH) + c;
        float P0=0.f, P1=0.f, P2=0.f, P3=0.f;
        #pragma unroll
        for (int rg = 0; rg < 4; rg++) {
            float w0 = __ldg(wp + (rg*4+0)*16);
            float w1 = __ldg(wp + (rg*4+1)*16);
            float w2 = __ldg(wp + (rg*4+2)*16);
            float w3 = __ldg(wp + (rg*4+3)*16);
            float4 a0 = *(const float4*)&s_sm[w][0][rg*4];
            float4 a1 = *(const float4*)&s_sm[w][1][rg*4];
            float4 a2 = *(const float4*)&s_sm[w][2][rg*4];
            float4 a3 = *(const float4*)&s_sm[w][3][rg*4];
            P0 = fmaf(a0.x,w0, fmaf(a0.y,w1, fmaf(a0.z,w2, fmaf(a0.w,w3, P0))));
            P1 = fmaf(a1.x,w0, fmaf(a1.y,w1, fmaf(a1.z,w2, fmaf(a1.w,w3, P1))));
            P2 = fmaf(a2.x,w0, fmaf(a2.y,w1, fmaf(a2.z,w2, fmaf(a2.w,w3, P2))));
            P3 = fmaf(a3.x,w0, fmaf(a3.y,w1, fmaf(a3.z,w2, fmaf(a3.w,w3, P3))));
        }
        __syncwarp();

        accP[0][0] = fmaf(P0, D0[0], accP[0][0]);
        accP[0][1] = fmaf(P0, D1[0], accP[0][1]);
        accP[0][2] = fmaf(P0, D2[0], accP[0][2]);
        accP[1][0] = fmaf(P1, D0[1], accP[1][0]);
        accP[1][1] = fmaf(P1, D1[1], accP[1][1]);
        accP[1][2] = fmaf(P1, D2[1], accP[1][2]);
        accP[2][0] = fmaf(P2, D0[2], accP[2][0]);
        accP[2][1] = fmaf(P2, D1[2], accP[2][1]);
        accP[2][2] = fmaf(P2, D2[2], accP[2][2]);
        accP[3][0] = fmaf(P3, D0[3], accP[3][0]);
        accP[3][1] = fmaf(P3, D1[3], accP[3][1]);
        accP[3][2] = fmaf(P3, D2[3], accP[3][2]);
    }

    float* outp = isQ ? g_bqp : g_bkp;
    #pragma unroll
    for (int t = 0; t < TI; t++)
        #pragma unroll
        for (int b = 0; b < 3; b++)
            outp[(js*NN + (i0+t))*48 + c*3 + b] = accP[t][b];
    if (!isQ) {
        #pragma unroll
        for (int t = 0; t < TI; t++)
            #pragma unroll
            for (int b = 0; b < 3; b++)
                g_Sp[(js*NN + (i0+t))*48 + c*3 + b] = accS[t][b];  // c == r
    }
}

// ---------------------------------------------------------------------------
// Phase B: merge partials, att = bk·bq outer, MLP1 -> g_lr; also merge S.
// ---------------------------------------------------------------------------
__global__ __launch_bounds__(256) void phaseB(const float* __restrict__ W1,
                                              const float* __restrict__ b1,
                                              const float* __restrict__ W2)
{
    const int i = blockIdx.x;
    const int tid = threadIdx.x;
    __shared__ float s_bk[48], s_bq[48], s_att[256], s_y[16];

    if (tid < 48) {
        float s = 0.f;
        #pragma unroll
        for (int js = 0; js < JS; js++) s += g_bkp[(js*NN + i)*48 + tid];
        s_bk[tid] = s;
    } else if (tid < 96) {
        float s = 0.f;
        #pragma unroll
        for (int js = 0; js < JS; js++) s += g_bqp[(js*NN + i)*48 + (tid-48)];
        s_bq[tid-48] = s;
    } else if (tid < 144) {
        float s = 0.f;
        #pragma unroll
        for (int js = 0; js < JS; js++) s += g_Sp[(js*NN + i)*48 + (tid-96)];
        g_S[i*48 + (tid-96)] = s;
    }
    __syncthreads();

    {
        int h = tid >> 4, g = tid & 15;
        s_att[tid] = s_bk[h*3+0]*s_bq[g*3+0] + s_bk[h*3+1]*s_bq[g*3+1]
                   + s_bk[h*3+2]*s_bq[g*3+2];
    }
    __syncthreads();

    {
        int h = tid >> 4, t = tid & 15;
        const float* w = W1 + h*256 + t;
        float p = 0.f;
        #pragma unroll
        for (int q = 0; q < 16; q++) p = fmaf(s_att[t + 16*q], w[16*q], p);
        #pragma unroll
        for (int m = 8; m >= 1; m >>= 1) p += __shfl_xor_sync(0xffffffffu, p, m, 16);
        if (t == 0) {
            float y = p + b1[h];
            s_y[h] = y / (1.0f + __expf(-y));
        }
    }
    __syncthreads();

    #pragma unroll
    for (int q = 0; q < 4; q++) {
        int m = tid + 256*q;
        const float* w = W2 + m*16;
        float a = 0.f;
        #pragma unroll
        for (int o = 0; o < 16; o++) a = fmaf(s_y[o], w[o], a);
        g_lr[i*1024 + m] = a;
    }
}

// ---------------------------------------------------------------------------
// Phase C: second contraction (right-stream part), shfl-free.
// ---------------------------------------------------------------------------
__global__ __launch_bounds__(BLK, 2) void phaseC()
{
    const int tid  = threadIdx.x;
    const int w    = tid >> 5;
    const int lane = tid & 31;
    const int wid  = blockIdx.x * (BLK/32) + w;
    const int ig   = wid >> 5;
    const int js   = wid & (JS-1);
    const int i0   = ig * TI;
    const int c    = lane & 15;
    const bool isQ = lane >= 16;
    (void)w;

    float accP[TI][3];
    #pragma unroll
    for (int t = 0; t < TI; t++)
        #pragma unroll
        for (int b = 0; b < 3; b++) accP[t][b] = 0.f;

    const int lroff = 512 + (isQ ? 256 : 0) + c;

    #pragma unroll 2
    for (int jl = 0; jl < JPW; jl++) {
        const int j = js * JPW + jl;
        const float* wp = g_lr + j*1024 + lroff;
        const float4* sm0 = (const float4*)&g_sm[((i0+0)*NN + j)*16];
        const float4* sm1 = (const float4*)&g_sm[((i0+1)*NN + j)*16];
        const float4* sm2 = (const float4*)&g_sm[((i0+2)*NN + j)*16];
        const float4* sm3 = (const float4*)&g_sm[((i0+3)*NN + j)*16];

        float P0=0.f, P1=0.f, P2=0.f, P3=0.f;
        #pragma unroll
        for (int rg = 0; rg < 4; rg++) {
            float w0 = __ldg(wp + (rg*4+0)*16);
            float w1 = __ldg(wp + (rg*4+1)*16);
            float w2 = __ldg(wp + (rg*4+2)*16);
            float w3 = __ldg(wp + (rg*4+3)*16);
            float4 a0 = __ldg(sm0 + rg);
            float4 a1 = __ldg(sm1 + rg);
            float4 a2 = __ldg(sm2 + rg);
            float4 a3 = __ldg(sm3 + rg);
            P0 = fmaf(a0.x,w0, fmaf(a0.y,w1, fmaf(a0.z,w2, fmaf(a0.w,w3, P0))));
            P1 = fmaf(a1.x,w0, fmaf(a1.y,w1, fmaf(a1.z,w2, fmaf(a1.w,w3, P1))));
            P2 = fmaf(a2.x,w0, fmaf(a2.y,w1, fmaf(a2.z,w2, fmaf(a2.w,w3, P2))));
            P3 = fmaf(a3.x,w0, fmaf(a3.y,w1, fmaf(a3.z,w2, fmaf(a3.w,w3, P3))));
        }

        float4 df0 = __ldg(&g_diffn4[(i0+0)*NN + j]);
        float4 df1 = __ldg(&g_diffn4[(i0+1)*NN + j]);
        float4 df2 = __ldg(&g_diffn4[(i0+2)*NN + j]);
        float4 df3 = __ldg(&g_diffn4[(i0+3)*NN + j]);

        accP[0][0] = fmaf(P0, df0.x, accP[0][0]);
        accP[0][1] = fmaf(P0, df0.y, accP[0][1]);
        accP[0][2] = fmaf(P0, df0.z, accP[0][2]);
        accP[1][0] = fmaf(P1, df1.x, accP[1][0]);
        accP[1][1] = fmaf(P1, df1.y, accP[1][1]);
        accP[1][2] = fmaf(P1, df1.z, accP[1][2]);
        accP[2][0] = fmaf(P2, df2.x, accP[2][0]);
        accP[2][1] = fmaf(P2, df2.y, accP[2][1]);
        accP[2][2] = fmaf(P2, df2.z, accP[2][2]);
        accP[3][0] = fmaf(P3, df3.x, accP[3][0]);
        accP[3][1] = fmaf(P3, df3.y, accP[3][1]);
        accP[3][2] = fmaf(P3, df3.z, accP[3][2]);
    }

    float* outp = isQ ? g_bq2p : g_bk2p;
    #pragma unroll
    for (int t = 0; t < TI; t++)
        #pragma unroll
        for (int b = 0; b < 3; b++)
            outp[(js*NN + (i0+t))*48 + c*3 + b] = accP[t][b];
}

// ---------------------------------------------------------------------------
// Phase D: merge partials + left⊗S term, att outer, MLP2, output.
// ---------------------------------------------------------------------------
__global__ __launch_bounds__(256) void phaseD(const float* __restrict__ W3,
                                              const float* __restrict__ b3,
                                              const float* __restrict__ W4,
                                              const float* __restrict__ b4,
                                              float* __restrict__ out)
{
    const int i = blockIdx.x;
    const int tid = threadIdx.x;
    __shared__ float s_bk[48], s_bq[48], s_att[256], s_y[16];

    if (tid < 48) {
        int cc = tid/3, b = tid%3;
        float s = 0.f;
        #pragma unroll
        for (int js = 0; js < JS; js++) s += g_bk2p[(js*NN + i)*48 + tid];
        const float* lp = g_lr + i*1024 + cc;        // left-K
        const float* sp = g_S  + i*48 + b;
        #pragma unroll
        for (int r = 0; r < 16; r++) s = fmaf(lp[r*16], sp[r*3], s);
        s_bk[tid] = s;
    } else if (tid < 96) {
        int idx = tid - 48, cc = idx/3, b = idx%3;
        float s = 0.f;
        #pragma unroll
        for (int js = 0; js < JS; js++) s += g_bq2p[(js*NN + i)*48 + idx];
        const float* lp = g_lr + i*1024 + 256 + cc;  // left-Q
        const float* sp = g_S  + i*48 + b;
        #pragma unroll
        for (int r = 0; r < 16; r++) s = fmaf(lp[r*16], sp[r*3], s);
        s_bq[idx] = s;
    }
    __syncthreads();

    {
        int h = tid >> 4, g = tid & 15;
        s_att[tid] = s_bk[h*3+0]*s_bq[g*3+0] + s_bk[h*3+1]*s_bq[g*3+1]
                   + s_bk[h*3+2]*s_bq[g*3+2];
    }
    __syncthreads();

    {
        int h = tid >> 4, t = tid & 15;
        const float* w = W3 + h*256 + t;
        float p = 0.f;
        #pragma unroll
        for (int q = 0; q < 16; q++) p = fmaf(s_att[t + 16*q], w[16*q], p);
        #pragma unroll
        for (int m = 8; m >= 1; m >>= 1) p += __shfl_xor_sync(0xffffffffu, p, m, 16);
        if (t == 0) {
            float y = p + b3[h];
            s_y[h] = y / (1.0f + __expf(-y));
        }
    }
    __syncthreads();

    if (tid == 0) {
        float a = b4[0];
        #pragma unroll
        for (int o = 0; o < 16; o++) a = fmaf(s_y[o], W4[o], a);
        out[i] = a;
    }
}

// ---------------------------------------------------------------------------
extern "C" void kernel_launch(void* const* d_in, const int* in_sizes, int n_in,
                              void* d_out, int out_size)
{
    const float* x  = (const float*)d_in[0];
    const float* W  = (const float*)d_in[1];
    const float* W1 = (const float*)d_in[2];
    const float* b1 = (const float*)d_in[3];
    const float* W2 = (const float*)d_in[4];
    const float* W3 = (const float*)d_in[5];
    const float* b3 = (const float*)d_in[6];
    const float* W4 = (const float*)d_in[7];
    const float* b4 = (const float*)d_in[8];
    float* out = (float*)d_out;

    phaseA<<<GRID_AC, BLK>>>(x, W);
    phaseB<<<NN, 256>>>(W1, b1, W2);
    phaseC<<<GRID_AC, BLK>>>();
    phaseD<<<NN, 256>>>(W3, b3, W4, b4, out);
}

// round 4
// speedup vs baseline: 4.4867x; 1.0764x over previous
#include <cuda_runtime.h>

#define NN 512
#define RR 16
#define HH 16
#define TI 4               // i-rows per warp
#define JS 16              // j slices (partial buffers)
#define JPW (NN/JS)        // 32 j per warp
#define JCH 16             // j's staged per chunk
#define NCH (JPW/JCH)      // 2 chunks
#define WPB 8              // warps per block
#define BLK 256
#define NIG (NN/TI)        // 128 i-groups
#define GRID_AC ((NIG/WPB)*JS)   // 16*16 = 256 blocks

// smearing constants (f32)
#define SM_START 0.006737946999085467f
#define SM_MSTEP ((1.0f - SM_START) * (1.0f/15.0f))
#define SM_SBETA (0.125f * (1.0f - SM_START))
#define SM_BETA  (1.0f / (SM_SBETA * SM_SBETA))
#define PI_OVER5 0.6283185307179586f

// scratch
__device__ __align__(16) float g_sm[NN*NN*RR];   // [i][j][r]  16MB
__device__ float4 g_diffn4[NN*NN];               // [i][j] -> (d0,d1,d2,0)
__device__ float g_bkp [JS*NN*48];
__device__ float g_bqp [JS*NN*48];
__device__ float g_Sp  [JS*NN*48];
__device__ float g_S   [NN*48];
__device__ float g_lr  [NN*1024];                // left(512)|right(512)
__device__ float g_bk2p[JS*NN*48];
__device__ float g_bq2p[JS*NN*48];

// ---------------------------------------------------------------------------
// Phase A: block = (ig-block of 8 warps, j-slice). W slice staged in smem.
// Warp w owns 4 i's; lanes 0-15 K path (c=lane), 16-31 Q path.
// ---------------------------------------------------------------------------
__global__ __launch_bounds__(BLK, 2) void phaseA(const float* __restrict__ x,
                                                 const float* __restrict__ W)
{
    __shared__ float s_x[NN*3];
    __shared__ __align__(16) float s_W[2*JCH*256];      // K | Q slice, 32KB
    __shared__ __align__(16) float s_sm[WPB][TI][RR];

    const int tid  = threadIdx.x;
    const int w    = tid >> 5;
    const int lane = tid & 31;
    const int igb  = blockIdx.x >> 4;        // / JS
    const int js   = blockIdx.x & (JS-1);
    const int i0   = (igb*WPB + w)*TI;
    const int c    = lane & 15;
    const bool isQ = lane >= 16;
    const float mean = SM_START + SM_MSTEP * (float)c;

    for (int k = tid; k < NN*3; k += BLK) s_x[k] = x[k];
    __syncthreads();

    float xi0[TI], xi1[TI], xi2[TI];
    #pragma unroll
    for (int t = 0; t < TI; t++) {
        xi0[t] = s_x[(i0+t)*3+0];
        xi1[t] = s_x[(i0+t)*3+1];
        xi2[t] = s_x[(i0+t)*3+2];
    }

    float accP[TI][3], accS[TI][3];
    #pragma unroll
    for (int t = 0; t < TI; t++)
        #pragma unroll
        for (int b = 0; b < 3; b++) { accP[t][b] = 0.f; accS[t][b] = 0.f; }

    for (int ch = 0; ch < NCH; ch++) {
        const int j0 = js*JPW + ch*JCH;
        __syncthreads();                       // prior chunk fully consumed
        {   // stage K[j0:j0+16], Q[j0:j0+16]  (each 4096 floats, contiguous)
            float4* dst = (float4*)s_W;
            const float4* srcK = (const float4*)(W + j0*(RR*HH));
            const float4* srcQ = (const float4*)(W + NN*RR*HH + j0*(RR*HH));
            #pragma unroll
            for (int f = 0; f < 4; f++) dst[tid + f*BLK]        = srcK[tid + f*BLK];
            #pragma unroll
            for (int f = 0; f < 4; f++) dst[1024 + tid + f*BLK] = srcQ[tid + f*BLK];
        }
        __syncthreads();

        #pragma unroll 2
        for (int jl = 0; jl < JCH; jl++) {
            const int j = j0 + jl;
            const float xj0 = s_x[j*3+0];
            const float xj1 = s_x[j*3+1];
            const float xj2 = s_x[j*3+2];

            float D0[TI], D1[TI], D2[TI];
            #pragma unroll
            for (int t = 0; t < TI; t++) {
                float dx = xi0[t]-xj0, dy = xi1[t]-xj1, dz = xi2[t]-xj2;
                float nsq = fmaf(dx,dx, fmaf(dy,dy, fmaf(dz,dz, 1e-6f)));
                float rin = rsqrtf(nsq);
                float d   = nsq * rin;
                float inv = rin * rin;
                D0[t] = dx*inv; D1[t] = dy*inv; D2[t] = dz*inv;
                float e   = __expf(-d);
                float cut = (d < 5.0f) ? 0.5f*(__cosf(d*PI_OVER5) + 1.0f) : 0.0f;
                float u   = e - mean;
                float sv  = cut * __expf(-SM_BETA*u*u);
                accS[t][0] = fmaf(sv, D0[t], accS[t][0]);
                accS[t][1] = fmaf(sv, D1[t], accS[t][1]);
                accS[t][2] = fmaf(sv, D2[t], accS[t][2]);
                if (!isQ) {
                    s_sm[w][t][c] = sv;
                    g_sm[((i0+t)*NN + j)*16 + c] = sv;
                }
                if (lane == 16+t)
                    g_diffn4[(i0+t)*NN + j] = make_float4(D0[t], D1[t], D2[t], 0.f);
            }
            __syncwarp();

            const float* wp = &s_W[(isQ ? JCH*256 : 0) + jl*256 + c];
            float P0=0.f, P1=0.f, P2=0.f, P3=0.f;
            #pragma unroll
            for (int rg = 0; rg < 4; rg++) {
                float w0 = wp[(rg*4+0)*16];
                float w1 = wp[(rg*4+1)*16];
                float w2 = wp[(rg*4+2)*16];
                float w3 = wp[(rg*4+3)*16];
                float4 a0 = *(const float4*)&s_sm[w][0][rg*4];
                float4 a1 = *(const float4*)&s_sm[w][1][rg*4];
                float4 a2 = *(const float4*)&s_sm[w][2][rg*4];
                float4 a3 = *(const float4*)&s_sm[w][3][rg*4];
                P0 = fmaf(a0.x,w0, fmaf(a0.y,w1, fmaf(a0.z,w2, fmaf(a0.w,w3, P0))));
                P1 = fmaf(a1.x,w0, fmaf(a1.y,w1, fmaf(a1.z,w2, fmaf(a1.w,w3, P1))));
                P2 = fmaf(a2.x,w0, fmaf(a2.y,w1, fmaf(a2.z,w2, fmaf(a2.w,w3, P2))));
                P3 = fmaf(a3.x,w0, fmaf(a3.y,w1, fmaf(a3.z,w2, fmaf(a3.w,w3, P3))));
            }

            accP[0][0] = fmaf(P0, D0[0], accP[0][0]);
            accP[0][1] = fmaf(P0, D1[0], accP[0][1]);
            accP[0][2] = fmaf(P0, D2[0], accP[0][2]);
            accP[1][0] = fmaf(P1, D0[1], accP[1][0]);
            accP[1][1] = fmaf(P1, D1[1], accP[1][1]);
            accP[1][2] = fmaf(P1, D2[1], accP[1][2]);
            accP[2][0] = fmaf(P2, D0[2], accP[2][0]);
            accP[2][1] = fmaf(P2, D1[2], accP[2][1]);
            accP[2][2] = fmaf(P2, D2[2], accP[2][2]);
            accP[3][0] = fmaf(P3, D0[3], accP[3][0]);
            accP[3][1] = fmaf(P3, D1[3], accP[3][1]);
            accP[3][2] = fmaf(P3, D2[3], accP[3][2]);
            __syncwarp();
        }
    }

    float* outp = isQ ? g_bqp : g_bkp;
    #pragma unroll
    for (int t = 0; t < TI; t++)
        #pragma unroll
        for (int b = 0; b < 3; b++)
            outp[(js*NN + (i0+t))*48 + c*3 + b] = accP[t][b];
    if (!isQ) {
        #pragma unroll
        for (int t = 0; t < TI; t++)
            #pragma unroll
            for (int b = 0; b < 3; b++)
                g_Sp[(js*NN + (i0+t))*48 + c*3 + b] = accS[t][b];  // c == r
    }
}

// ---------------------------------------------------------------------------
// Phase B: merge partials, att outer, MLP1 -> g_lr; merge S.
// ---------------------------------------------------------------------------
__global__ __launch_bounds__(256) void phaseB(const float* __restrict__ W1,
                                              const float* __restrict__ b1,
                                              const float* __restrict__ W2)
{
    const int i = blockIdx.x;
    const int tid = threadIdx.x;
    __shared__ float s_bk[48], s_bq[48], s_att[256], s_y[16];

    if (tid < 48) {
        float s = 0.f;
        #pragma unroll
        for (int js = 0; js < JS; js++) s += g_bkp[(js*NN + i)*48 + tid];
        s_bk[tid] = s;
    } else if (tid < 96) {
        float s = 0.f;
        #pragma unroll
        for (int js = 0; js < JS; js++) s += g_bqp[(js*NN + i)*48 + (tid-48)];
        s_bq[tid-48] = s;
    } else if (tid < 144) {
        float s = 0.f;
        #pragma unroll
        for (int js = 0; js < JS; js++) s += g_Sp[(js*NN + i)*48 + (tid-96)];
        g_S[i*48 + (tid-96)] = s;
    }
    __syncthreads();

    {
        int h = tid >> 4, g = tid & 15;
        s_att[tid] = s_bk[h*3+0]*s_bq[g*3+0] + s_bk[h*3+1]*s_bq[g*3+1]
                   + s_bk[h*3+2]*s_bq[g*3+2];
    }
    __syncthreads();

    {
        int h = tid >> 4, t = tid & 15;
        const float* w = W1 + h*256 + t;
        float p = 0.f;
        #pragma unroll
        for (int q = 0; q < 16; q++) p = fmaf(s_att[t + 16*q], w[16*q], p);
        #pragma unroll
        for (int m = 8; m >= 1; m >>= 1) p += __shfl_xor_sync(0xffffffffu, p, m, 16);
        if (t == 0) {
            float y = p + b1[h];
            s_y[h] = y / (1.0f + __expf(-y));
        }
    }
    __syncthreads();

    #pragma unroll
    for (int q = 0; q < 4; q++) {
        int m = tid + 256*q;
        const float* w = W2 + m*16;
        float a = 0.f;
        #pragma unroll
        for (int o = 0; o < 16; o++) a = fmaf(s_y[o], w[o], a);
        g_lr[i*1024 + m] = a;
    }
}

// ---------------------------------------------------------------------------
// Phase C: second contraction, right-stream. lr-right slice staged in smem;
// sm/diffn gathered with one predicated LDG.128 per (warp, j).
// ---------------------------------------------------------------------------
__global__ __launch_bounds__(BLK, 2) void phaseC()
{
    __shared__ __align__(16) float s_R[JCH*512];        // right slice, 32KB
    __shared__ __align__(16) float4 s_smT[WPB][TI][4];
    __shared__ __align__(16) float4 s_df[WPB][TI];

    const int tid  = threadIdx.x;
    const int w    = tid >> 5;
    const int lane = tid & 31;
    const int igb  = blockIdx.x >> 4;
    const int js   = blockIdx.x & (JS-1);
    const int i0   = (igb*WPB + w)*TI;
    const int c    = lane & 15;
    const bool isQ = lane >= 16;

    float accP[TI][3];
    #pragma unroll
    for (int t = 0; t < TI; t++)
        #pragma unroll
        for (int b = 0; b < 3; b++) accP[t][b] = 0.f;

    for (int ch = 0; ch < NCH; ch++) {
        const int j0 = js*JPW + ch*JCH;
        __syncthreads();
        {   // stage right part of lr for 16 j's: g_lr[j][512..1023]
            float4* dst = (float4*)s_R;
            const float4* src = (const float4*)g_lr;
            #pragma unroll
            for (int f = 0; f < 8; f++) {
                int idx = tid + f*BLK;             // 0..2047
                int jl = idx >> 7, o = idx & 127;
                dst[idx] = src[(j0+jl)*256 + 128 + o];
            }
        }
        __syncthreads();

        #pragma unroll 2
        for (int jl = 0; jl < JCH; jl++) {
            const int j = j0 + jl;
            if (lane < 16) {
                int t = lane >> 2, rg = lane & 3;
                s_smT[w][t][rg] = *(const float4*)&g_sm[((i0+t)*NN + j)*16 + rg*4];
            } else if (lane < 20) {
                s_df[w][lane-16] = g_diffn4[(i0 + lane-16)*NN + j];
            }
            __syncwarp();

            const float* wp = &s_R[jl*512 + (isQ ? 256 : 0) + c];
            float P0=0.f, P1=0.f, P2=0.f, P3=0.f;
            #pragma unroll
            for (int rg = 0; rg < 4; rg++) {
                float w0 = wp[(rg*4+0)*16];
                float w1 = wp[(rg*4+1)*16];
                float w2 = wp[(rg*4+2)*16];
                float w3 = wp[(rg*4+3)*16];
                float4 a0 = s_smT[w][0][rg];
                float4 a1 = s_smT[w][1][rg];
                float4 a2 = s_smT[w][2][rg];
                float4 a3 = s_smT[w][3][rg];
                P0 = fmaf(a0.x,w0, fmaf(a0.y,w1, fmaf(a0.z,w2, fmaf(a0.w,w3, P0))));
                P1 = fmaf(a1.x,w0, fmaf(a1.y,w1, fmaf(a1.z,w2, fmaf(a1.w,w3, P1))));
                P2 = fmaf(a2.x,w0, fmaf(a2.y,w1, fmaf(a2.z,w2, fmaf(a2.w,w3, P2))));
                P3 = fmaf(a3.x,w0, fmaf(a3.y,w1, fmaf(a3.z,w2, fmaf(a3.w,w3, P3))));
            }

            float4 df0 = s_df[w][0], df1 = s_df[w][1];
            float4 df2 = s_df[w][2], df3 = s_df[w][3];
            accP[0][0] = fmaf(P0, df0.x, accP[0][0]);
            accP[0][1] = fmaf(P0, df0.y, accP[0][1]);
            accP[0][2] = fmaf(P0, df0.z, accP[0][2]);
            accP[1][0] = fmaf(P1, df1.x, accP[1][0]);
            accP[1][1] = fmaf(P1, df1.y, accP[1][1]);
            accP[1][2] = fmaf(P1, df1.z, accP[1][2]);
            accP[2][0] = fmaf(P2, df2.x, accP[2][0]);
            accP[2][1] = fmaf(P2, df2.y, accP[2][1]);
            accP[2][2] = fmaf(P2, df2.z, accP[2][2]);
            accP[3][0] = fmaf(P3, df3.x, accP[3][0]);
            accP[3][1] = fmaf(P3, df3.y, accP[3][1]);
            accP[3][2] = fmaf(P3, df3.z, accP[3][2]);
            __syncwarp();
        }
    }

    float* outp = isQ ? g_bq2p : g_bk2p;
    #pragma unroll
    for (int t = 0; t < TI; t++)
        #pragma unroll
        for (int b = 0; b < 3; b++)
            outp[(js*NN + (i0+t))*48 + c*3 + b] = accP[t][b];
}

// ---------------------------------------------------------------------------
// Phase D: merge partials + left⊗S term, att outer, MLP2, output.
// ---------------------------------------------------------------------------
__global__ __launch_bounds__(256) void phaseD(const float* __restrict__ W3,
                                              const float* __restrict__ b3,
                                              const float* __restrict__ W4,
                                              const float* __restrict__ b4,
                                              float* __restrict__ out)
{
    const int i = blockIdx.x;
    const int tid = threadIdx.x;
    __shared__ float s_bk[48], s_bq[48], s_att[256], s_y[16];

    if (tid < 48) {
        int cc = tid/3, b = tid%3;
        float s = 0.f;
        #pragma unroll
        for (int js = 0; js < JS; js++) s += g_bk2p[(js*NN + i)*48 + tid];
        const float* lp = g_lr + i*1024 + cc;        // left-K
        const float* sp = g_S  + i*48 + b;
        #pragma unroll
        for (int r = 0; r < 16; r++) s = fmaf(lp[r*16], sp[r*3], s);
        s_bk[tid] = s;
    } else if (tid < 96) {
        int idx = tid - 48, cc = idx/3, b = idx%3;
        float s = 0.f;
        #pragma unroll
        for (int js = 0; js < JS; js++) s += g_bq2p[(js*NN + i)*48 + idx];
        const float* lp = g_lr + i*1024 + 256 + cc;  // left-Q
        const float* sp = g_S  + i*48 + b;
        #pragma unroll
        for (int r = 0; r < 16; r++) s = fmaf(lp[r*16], sp[r*3], s);
        s_bq[idx] = s;
    }
    __syncthreads();

    {
        int h = tid >> 4, g = tid & 15;
        s_att[tid] = s_bk[h*3+0]*s_bq[g*3+0] + s_bk[h*3+1]*s_bq[g*3+1]
                   + s_bk[h*3+2]*s_bq[g*3+2];
    }
    __syncthreads();

    {
        int h = tid >> 4, t = tid & 15;
        const float* w = W3 + h*256 + t;
        float p = 0.f;
        #pragma unroll
        for (int q = 0; q < 16; q++) p = fmaf(s_att[t + 16*q], w[16*q], p);
        #pragma unroll
        for (int m = 8; m >= 1; m >>= 1) p += __shfl_xor_sync(0xffffffffu, p, m, 16);
        if (t == 0) {
            float y = p + b3[h];
            s_y[h] = y / (1.0f + __expf(-y));
        }
    }
    __syncthreads();

    if (tid == 0) {
        float a = b4[0];
        #pragma unroll
        for (int o = 0; o < 16; o++) a = fmaf(s_y[o], W4[o], a);
        out[i] = a;
    }
}

// ---------------------------------------------------------------------------
extern "C" void kernel_launch(void* const* d_in, const int* in_sizes, int n_in,
                              void* d_out, int out_size)
{
    const float* x  = (const float*)d_in[0];
    const float* W  = (const float*)d_in[1];
    const float* W1 = (const float*)d_in[2];
    const float* b1 = (const float*)d_in[3];
    const float* W2 = (const float*)d_in[4];
    const float* W3 = (const float*)d_in[5];
    const float* b3 = (const float*)d_in[6];
    const float* W4 = (const float*)d_in[7];
    const float* b4 = (const float*)d_in[8];
    float* out = (float*)d_out;

    phaseA<<<GRID_AC, BLK>>>(x, W);
    phaseB<<<NN, 256>>>(W1, b1, W2);
    phaseC<<<GRID_AC, BLK>>>();
    phaseD<<<NN, 256>>>(W3, b3, W4, b4, out);
}